// round 1
// baseline (speedup 1.0000x reference)
#include <cuda_runtime.h>
#include <math.h>

// Problem constants (from reference setup_inputs): B=4, R=4096, S=96, C=32
#define RAYS   16384      // B*R
#define NS     96         // samples per ray
#define NC     32         // color channels
#define SM1    95         // S-1
#define EPSV   1e-10f

// Global min/max of depths (bit-pattern trick: all depths > 0, so uint order == float order)
__device__ unsigned int g_minbits;
__device__ unsigned int g_maxbits;

__global__ void mrm_init_minmax() {
    g_minbits = 0xFFFFFFFFu;   // larger than any positive-float bit pattern
    g_maxbits = 0u;
}

// depths are sorted along the sample axis, so global min = min over sample 0,
// global max = max over sample S-1.
__global__ void mrm_reduce_minmax(const float* __restrict__ depths) {
    int r = blockIdx.x * blockDim.x + threadIdx.x;
    unsigned int mn = 0xFFFFFFFFu, mx = 0u;
    if (r < RAYS) {
        mn = __float_as_uint(depths[r * NS]);
        mx = __float_as_uint(depths[r * NS + (NS - 1)]);
    }
    #pragma unroll
    for (int o = 16; o > 0; o >>= 1) {
        mn = min(mn, __shfl_xor_sync(0xFFFFFFFFu, mn, o));
        mx = max(mx, __shfl_xor_sync(0xFFFFFFFFu, mx, o));
    }
    if ((threadIdx.x & 31) == 0) {
        atomicMin(&g_minbits, mn);
        atomicMax(&g_maxbits, mx);
    }
}

// One warp per ray. 8 warps (8 rays) per block.
__global__ __launch_bounds__(256) void mrm_march(
    const float* __restrict__ colors,     // [RAYS, NS, NC]
    const float* __restrict__ densities,  // [RAYS, NS]
    const float* __restrict__ depths,     // [RAYS, NS]
    float* __restrict__ out)
{
    __shared__ float s_alpha[8][SM1 + 1];
    __shared__ float s_dmid [8][SM1 + 1];
    __shared__ float s_w    [8][SM1 + 1];

    const int warp = threadIdx.x >> 5;
    const int lane = threadIdx.x & 31;
    const int ray  = blockIdx.x * 8 + warp;

    const float* dR = depths    + (size_t)ray * NS;
    const float* nR = densities + (size_t)ray * NS;

    // ---- Phase 1: per-sample alpha + depth midpoint into shared ----
    for (int j = lane; j < SM1; j += 32) {
        float d0 = dR[j],  d1 = dR[j + 1];
        float n0 = nR[j],  n1 = nR[j + 1];
        float delta = d1 - d0;
        float dm    = 0.5f * (d0 + d1);
        float nm    = 0.5f * (n0 + n1) - 1.0f;
        // softplus (overflow-safe)
        float sp    = (nm > 20.0f) ? nm : log1pf(expf(nm));
        float a     = 1.0f - expf(-sp * delta);
        s_alpha[warp][j] = a;
        s_dmid [warp][j] = dm;
    }
    __syncwarp();

    // ---- Phase 2: sequential transmittance scan; lane c owns channel c ----
    const float* cR = colors + (size_t)ray * NS * NC + lane;
    float cprev = cR[0];
    float T = 1.0f, rgb = 0.0f, wsum = 0.0f, dacc = 0.0f;

    #pragma unroll 5
    for (int i = 0; i < SM1; i++) {
        float cnext = cR[(size_t)(i + 1) * NC];      // coalesced 128B per warp
        float a = s_alpha[warp][i];                  // broadcast
        float w = a * T;
        T *= (1.0f - a + EPSV);
        float cmid = 0.5f * (cprev + cnext);
        rgb  = fmaf(w, cmid, rgb);
        wsum += w;
        dacc = fmaf(w, s_dmid[warp][i], dacc);
        if (lane == 0) s_w[warp][i] = w;
        cprev = cnext;
    }
    __syncwarp();

    // ---- Output layout: concat(rgb, depth, weights, alpha, weight_bg) ----
    float* out_rgb = out;                               // RAYS*NC
    float* out_dep = out_rgb + (size_t)RAYS * NC;       // RAYS
    float* out_w   = out_dep + RAYS;                    // RAYS*SM1
    float* out_a   = out_w   + (size_t)RAYS * SM1;      // RAYS*SM1
    float* out_bg  = out_a   + (size_t)RAYS * SM1;      // RAYS

    out_rgb[(size_t)ray * NC + lane] = rgb * 2.0f - 1.0f;

    if (lane == 0) {
        float dep = dacc / wsum;
        if (isnan(dep)) dep = INFINITY;
        float gmin = __uint_as_float(g_minbits);
        float gmax = __uint_as_float(g_maxbits);
        dep = fminf(fmaxf(dep, gmin), gmax);
        out_dep[ray] = dep;
        out_bg[ray]  = T;   // transmittance after all samples = weight_bg
    }

    for (int j = lane; j < SM1; j += 32) {
        out_w[(size_t)ray * SM1 + j] = s_w[warp][j];
        out_a[(size_t)ray * SM1 + j] = s_alpha[warp][j];
    }
}

extern "C" void kernel_launch(void* const* d_in, const int* in_sizes, int n_in,
                              void* d_out, int out_size) {
    const float* colors    = (const float*)d_in[0];
    const float* densities = (const float*)d_in[1];
    const float* depths    = (const float*)d_in[2];
    float* out = (float*)d_out;

    mrm_init_minmax<<<1, 1>>>();
    mrm_reduce_minmax<<<(RAYS + 255) / 256, 256>>>(depths);
    mrm_march<<<RAYS / 8, 256>>>(colors, densities, depths, out);
}

// round 2
// speedup vs baseline: 1.2752x; 1.2752x over previous
#include <cuda_runtime.h>
#include <math.h>

// Problem constants (B=4, R=4096, S=96, C=32)
#define RAYS   16384      // B*R
#define NS     96
#define NC     32
#define SM1    95         // S-1
#define EPSV   1e-10f
#define FULLM  0xFFFFFFFFu

// One warp per ray, 8 rays per block. Single kernel, no global min/max pass:
// composite_depth is a convex combination of this ray's depths_mid, so clamping
// to the ray's own [d0, d95] (subset of the global range) is equivalent to the
// reference's global clamp whenever wsum > 0 (always true: softplus > 0,
// depths strictly sorted).
__global__ __launch_bounds__(256) void mrm_fused(
    const float* __restrict__ colors,     // [RAYS, NS, NC]
    const float* __restrict__ densities,  // [RAYS, NS]
    const float* __restrict__ depths,     // [RAYS, NS]
    float* __restrict__ out)
{
    __shared__ float s_alpha[8][NS];   // 95 used
    __shared__ float s_dmid [8][NS];
    __shared__ float s_w    [8][NS];

    const int warp = threadIdx.x >> 5;
    const int lane = threadIdx.x & 31;
    const int ray  = blockIdx.x * 8 + warp;

    const float* dR = depths    + (size_t)ray * NS;
    const float* nR = densities + (size_t)ray * NS;

    // ---- Phase 1: alpha + depth midpoints (parallel over lanes) ----
    #pragma unroll
    for (int j = lane; j < SM1; j += 32) {
        float d0 = dR[j],  d1 = dR[j + 1];
        float n0 = nR[j],  n1 = nR[j + 1];
        float delta = d1 - d0;
        float nm    = 0.5f * (n0 + n1) - 1.0f;
        float sp    = (nm > 20.0f) ? nm : log1pf(expf(nm));   // softplus
        float a     = 1.0f - expf(-sp * delta);
        s_alpha[warp][j] = a;
        s_dmid [warp][j] = 0.5f * (d0 + d1);
    }
    __syncwarp();

    // ---- Phase 2: warp-parallel transmittance scan ----
    // Lane l owns contiguous samples [3l, 3l+cnt), cnt=3 (lane 31: 2).
    const int base = 3 * lane;
    const int cnt  = (lane == 31) ? 2 : 3;
    float a0 = s_alpha[warp][base];
    float a1 = s_alpha[warp][base + 1];
    float a2 = (cnt == 3) ? s_alpha[warp][base + 2] : 0.0f;
    float f0 = 1.0f - a0 + EPSV;
    float f1 = 1.0f - a1 + EPSV;
    float f2 = (cnt == 3) ? (1.0f - a2 + EPSV) : 1.0f;
    float p  = f0 * f1 * f2;

    // inclusive prefix product across lanes
    float x = p;
    #pragma unroll
    for (int o = 1; o < 32; o <<= 1) {
        float y = __shfl_up_sync(FULLM, x, o);
        if (lane >= o) x *= y;
    }
    float excl = __shfl_up_sync(FULLM, x, 1);
    if (lane == 0) excl = 1.0f;
    float Tbg = __shfl_sync(FULLM, x, 31);   // transmittance after all samples

    float T0 = excl;
    float w0 = a0 * T0;
    float T1 = T0 * f0;
    float w1 = a1 * T1;
    float T2 = T1 * f1;
    float w2 = (cnt == 3) ? a2 * T2 : 0.0f;

    s_w[warp][base]     = w0;
    s_w[warp][base + 1] = w1;
    if (cnt == 3) s_w[warp][base + 2] = w2;

    float wsum = w0 + w1 + w2;
    float dacc = w0 * s_dmid[warp][base] + w1 * s_dmid[warp][base + 1];
    if (cnt == 3) dacc = fmaf(w2, s_dmid[warp][base + 2], dacc);
    #pragma unroll
    for (int o = 16; o > 0; o >>= 1) {
        wsum += __shfl_xor_sync(FULLM, wsum, o);
        dacc += __shfl_xor_sync(FULLM, dacc, o);
    }
    __syncwarp();

    // ---- Phase 3: color pass as a pure weighted reduction ----
    // rgb_c = 0.5 * sum_j v_j * c_{j,c},  v_j = w_{j-1} + w_j (w_{-1}=w_95=0)
    // Lane layout: sub = lane>>3 picks one of 4 samples per iteration,
    // ch = lane&7 picks a float4 of channels. Warp reads 512B contiguous/iter.
    const float4* c4 = (const float4*)(colors + (size_t)ray * NS * NC);
    const int sub = lane >> 3;
    const int ch  = lane & 7;
    float4 acc = make_float4(0.f, 0.f, 0.f, 0.f);

    #pragma unroll
    for (int it = 0; it < NS / 4; it++) {
        int i = it * 4 + sub;
        float4 c = c4[i * 8 + ch];
        float wl = (i > 0)   ? s_w[warp][i - 1] : 0.0f;
        float wr = (i < SM1) ? s_w[warp][i]     : 0.0f;
        float v  = wl + wr;
        acc.x = fmaf(v, c.x, acc.x);
        acc.y = fmaf(v, c.y, acc.y);
        acc.z = fmaf(v, c.z, acc.z);
        acc.w = fmaf(v, c.w, acc.w);
    }
    // reduce across the 4 sample-groups (lanes ch, ch+8, ch+16, ch+24)
    #pragma unroll
    for (int o = 8; o <= 16; o <<= 1) {
        acc.x += __shfl_xor_sync(FULLM, acc.x, o);
        acc.y += __shfl_xor_sync(FULLM, acc.y, o);
        acc.z += __shfl_xor_sync(FULLM, acc.z, o);
        acc.w += __shfl_xor_sync(FULLM, acc.w, o);
    }

    // ---- Outputs: concat(rgb, depth, weights, alpha, weight_bg) ----
    float* out_rgb = out;                               // RAYS*NC
    float* out_dep = out_rgb + (size_t)RAYS * NC;       // RAYS
    float* out_w   = out_dep + RAYS;                    // RAYS*SM1
    float* out_a   = out_w   + (size_t)RAYS * SM1;      // RAYS*SM1
    float* out_bg  = out_a   + (size_t)RAYS * SM1;      // RAYS

    if (sub == 0) {
        // out = 2*(0.5*acc) - 1 = acc - 1
        float4 r = make_float4(acc.x - 1.f, acc.y - 1.f, acc.z - 1.f, acc.w - 1.f);
        ((float4*)(out_rgb + (size_t)ray * NC))[ch] = r;
    }

    if (lane == 0) {
        float dep = dacc / wsum;
        if (isnan(dep)) dep = INFINITY;
        dep = fminf(fmaxf(dep, dR[0]), dR[NS - 1]);   // == global clamp (see header)
        out_dep[ray] = dep;
        out_bg[ray]  = Tbg;
    }

    #pragma unroll
    for (int j = lane; j < SM1; j += 32) {
        out_w[(size_t)ray * SM1 + j] = s_w[warp][j];
        out_a[(size_t)ray * SM1 + j] = s_alpha[warp][j];
    }
}

extern "C" void kernel_launch(void* const* d_in, const int* in_sizes, int n_in,
                              void* d_out, int out_size) {
    const float* colors    = (const float*)d_in[0];
    const float* densities = (const float*)d_in[1];
    const float* depths    = (const float*)d_in[2];
    mrm_fused<<<RAYS / 8, 256>>>(colors, densities, depths, (float*)d_out);
}

// round 3
// speedup vs baseline: 1.4860x; 1.1653x over previous
#include <cuda_runtime.h>
#include <math.h>

// Problem constants (B=4, R=4096, S=96, C=32)
#define RAYS   16384      // B*R
#define NS     96
#define NC     32
#define SM1    95
#define EPSV   1e-10f
#define FULLM  0xFFFFFFFFu

// One warp per ray, 8 rays/block, single kernel.
// Math identities (validated in prior rounds, rel_err 3.4e-6):
//  - rgb_c = sum_j v_j * c_{j,c} - 1,  v_j = w_{j-1} + w_j  (w_{-1} = w_95 = 0)
//  - composite_depth is a convex combination of this ray's depths_mid, so the
//    reference's global clamp == clamp to this ray's own [d0, d95].
__global__ __launch_bounds__(256) void mrm_fused(
    const float* __restrict__ colors,     // [RAYS, NS, NC]
    const float* __restrict__ densities,  // [RAYS, NS]
    const float* __restrict__ depths,     // [RAYS, NS]
    float* __restrict__ out)
{
    __shared__ float s_d    [8][NS];
    __shared__ float s_n    [8][NS];
    __shared__ float s_alpha[8][NS];
    __shared__ float s_w    [8][NS];
    __shared__ float s_v    [8][NS];

    const int warp = threadIdx.x >> 5;
    const int lane = threadIdx.x & 31;
    const int ray  = blockIdx.x * 8 + warp;

    // ---- Kernel entry: fire ALL long-latency loads first ----
    // depths/densities: 24 float4 per ray, lanes 0..23, fully coalesced.
    const float4* d4 = (const float4*)(depths    + (size_t)ray * NS);
    const float4* n4 = (const float4*)(densities + (size_t)ray * NS);
    float4 dv, nv;
    if (lane < NS / 4) { dv = d4[lane]; nv = n4[lane]; }

    // colors batch 0 (samples [0,32)): 8 float4 per lane, in flight during scan.
    // sub = which of 4 samples per iter, ch = which float4 of channels.
    const float4* c4 = (const float4*)(colors + (size_t)ray * NS * NC);
    const int sub = lane >> 3;
    const int ch  = lane & 7;
    float4 buf[8];
    #pragma unroll
    for (int k = 0; k < 8; k++)
        buf[k] = c4[(size_t)((k << 2) + sub) * 8 + ch];

    if (lane < NS / 4) {
        ((float4*)s_d[warp])[lane] = dv;
        ((float4*)s_n[warp])[lane] = nv;
    }
    __syncwarp();

    // ---- Phase 1: alpha (parallel over lanes, from shared) ----
    #pragma unroll
    for (int j = lane; j < SM1; j += 32) {
        float delta = s_d[warp][j + 1] - s_d[warp][j];
        float nm    = 0.5f * (s_n[warp][j] + s_n[warp][j + 1]) - 1.0f;
        float sp    = (nm > 20.0f) ? nm : log1pf(expf(nm));   // softplus
        s_alpha[warp][j] = 1.0f - expf(-sp * delta);
    }
    __syncwarp();

    // ---- Phase 2: warp-parallel transmittance scan ----
    const int base = 3 * lane;
    const int cnt  = (lane == 31) ? 2 : 3;
    float a0 = s_alpha[warp][base];
    float a1 = s_alpha[warp][base + 1];
    float a2 = (cnt == 3) ? s_alpha[warp][base + 2] : 0.0f;
    float f0 = 1.0f - a0 + EPSV;
    float f1 = 1.0f - a1 + EPSV;
    float f2 = (cnt == 3) ? (1.0f - a2 + EPSV) : 1.0f;

    float x = f0 * f1 * f2;                // inclusive prefix product over lanes
    #pragma unroll
    for (int o = 1; o < 32; o <<= 1) {
        float y = __shfl_up_sync(FULLM, x, o);
        if (lane >= o) x *= y;
    }
    float T0 = __shfl_up_sync(FULLM, x, 1);
    if (lane == 0) T0 = 1.0f;
    float Tbg = __shfl_sync(FULLM, x, 31);

    float w0 = a0 * T0;
    float T1 = T0 * f0;
    float w1 = a1 * T1;
    float w2 = (cnt == 3) ? a2 * (T1 * f1) : 0.0f;

    s_w[warp][base]     = w0;
    s_w[warp][base + 1] = w1;
    if (cnt == 3) s_w[warp][base + 2] = w2;

    float dm0 = 0.5f * (s_d[warp][base]     + s_d[warp][base + 1]);
    float dm1 = 0.5f * (s_d[warp][base + 1] + s_d[warp][base + 2]);
    float wsum = w0 + w1 + w2;
    float dacc = w0 * dm0 + w1 * dm1;
    if (cnt == 3) {
        float dm2 = 0.5f * (s_d[warp][base + 2] + s_d[warp][base + 3]);
        dacc = fmaf(w2, dm2, dacc);
    }
    #pragma unroll
    for (int o = 16; o > 0; o >>= 1) {
        wsum += __shfl_xor_sync(FULLM, wsum, o);
        dacc += __shfl_xor_sync(FULLM, dacc, o);
    }
    __syncwarp();

    // v_j = w_{j-1} + w_j (needs neighbor lanes' w -> after syncwarp)
    #pragma unroll
    for (int j = lane; j < NS; j += 32) {
        float wl = (j > 0)   ? s_w[warp][j - 1] : 0.0f;
        float wr = (j < SM1) ? s_w[warp][j]     : 0.0f;
        s_v[warp][j] = wl + wr;
    }
    __syncwarp();

    // ---- Phase 3: software-pipelined weighted color reduction ----
    // Batch b covers samples [b*32, (b+1)*32); 8 float4 loads live per stage.
    float4 acc = make_float4(0.f, 0.f, 0.f, 0.f);
    #pragma unroll
    for (int b = 0; b < 3; b++) {
        float4 nbuf[8];
        if (b < 2) {
            #pragma unroll
            for (int k = 0; k < 8; k++)
                nbuf[k] = c4[(size_t)((b + 1) * 32 + (k << 2) + sub) * 8 + ch];
        }
        #pragma unroll
        for (int k = 0; k < 8; k++) {
            float v = s_v[warp][b * 32 + (k << 2) + sub];
            acc.x = fmaf(v, buf[k].x, acc.x);
            acc.y = fmaf(v, buf[k].y, acc.y);
            acc.z = fmaf(v, buf[k].z, acc.z);
            acc.w = fmaf(v, buf[k].w, acc.w);
        }
        if (b < 2) {
            #pragma unroll
            for (int k = 0; k < 8; k++) buf[k] = nbuf[k];
        }
    }
    // reduce across the 4 sample-groups (lanes ch, ch+8, ch+16, ch+24)
    #pragma unroll
    for (int o = 8; o <= 16; o <<= 1) {
        acc.x += __shfl_xor_sync(FULLM, acc.x, o);
        acc.y += __shfl_xor_sync(FULLM, acc.y, o);
        acc.z += __shfl_xor_sync(FULLM, acc.z, o);
        acc.w += __shfl_xor_sync(FULLM, acc.w, o);
    }

    // ---- Outputs: concat(rgb, depth, weights, alpha, weight_bg) ----
    float* out_rgb = out;                               // RAYS*NC
    float* out_dep = out_rgb + (size_t)RAYS * NC;       // RAYS
    float* out_w   = out_dep + RAYS;                    // RAYS*SM1
    float* out_a   = out_w   + (size_t)RAYS * SM1;      // RAYS*SM1
    float* out_bg  = out_a   + (size_t)RAYS * SM1;      // RAYS

    if (sub == 0) {
        float4 r = make_float4(acc.x - 1.f, acc.y - 1.f, acc.z - 1.f, acc.w - 1.f);
        ((float4*)(out_rgb + (size_t)ray * NC))[ch] = r;
    }

    if (lane == 0) {
        float dep = dacc / wsum;
        if (isnan(dep)) dep = INFINITY;
        dep = fminf(fmaxf(dep, s_d[warp][0]), s_d[warp][NS - 1]);
        out_dep[ray] = dep;
        out_bg[ray]  = Tbg;
    }

    #pragma unroll
    for (int j = lane; j < SM1; j += 32) {
        out_w[(size_t)ray * SM1 + j] = s_w[warp][j];
        out_a[(size_t)ray * SM1 + j] = s_alpha[warp][j];
    }
}

extern "C" void kernel_launch(void* const* d_in, const int* in_sizes, int n_in,
                              void* d_out, int out_size) {
    const float* colors    = (const float*)d_in[0];
    const float* densities = (const float*)d_in[1];
    const float* depths    = (const float*)d_in[2];
    mrm_fused<<<RAYS / 8, 256>>>(colors, densities, depths, (float*)d_out);
}

// round 4
// speedup vs baseline: 1.5353x; 1.0331x over previous
#include <cuda_runtime.h>
#include <math.h>

// Problem constants (B=4, R=4096, S=96, C=32)
#define RAYS   16384
#define NS     96
#define NC     32
#define SM1    95
#define EPSV   1e-10f
#define FULLM  0xFFFFFFFFu

// One warp per ray, 8 rays/block.
// Identities (validated, rel_err 3.4e-6):
//  - rgb_c = sum_j v_j*c_{j,c} - 1, v_j = w_{j-1}+w_j (w_{-1}=w_95=0)
//  - global depth clamp == per-ray [d0,d95] clamp (convex combination).
__global__ __launch_bounds__(256, 5) void mrm_fused(
    const float* __restrict__ colors,     // [RAYS, NS, NC]
    const float* __restrict__ densities,  // [RAYS, NS]
    const float* __restrict__ depths,     // [RAYS, NS]
    float* __restrict__ out)
{
    __shared__ float s_d    [8][NS];
    __shared__ float s_n    [8][NS];
    __shared__ float s_alpha[8][NS];
    __shared__ float s_w    [8][NS];
    __shared__ float s_v    [8][NS];

    const int warp = threadIdx.x >> 5;
    const int lane = threadIdx.x & 31;
    const int ray  = blockIdx.x * 8 + warp;

    // ---- Entry: fire long-latency loads first ----
    const float4* d4 = (const float4*)(depths    + (size_t)ray * NS);
    const float4* n4 = (const float4*)(densities + (size_t)ray * NS);
    float4 dv, nv;
    if (lane < NS / 4) { dv = d4[lane]; nv = n4[lane]; }

    // colors batch 0 (samples [0,24)): 6 float4/lane in flight during scan
    const float4* c4 = (const float4*)(colors + (size_t)ray * NS * NC);
    const int sub = lane >> 3;     // sample sub-group 0..3
    const int ch  = lane & 7;      // float4-of-channels 0..7
    float4 buf[6];
    #pragma unroll
    for (int k = 0; k < 6; k++)
        buf[k] = c4[(size_t)((k << 2) + sub) * 8 + ch];

    if (lane < NS / 4) {
        ((float4*)s_d[warp])[lane] = dv;
        ((float4*)s_n[warp])[lane] = nv;
    }
    __syncwarp();

    // ---- Merged phase 1+2: per-lane alphas + warp transmittance scan ----
    // Lane l owns samples [3l, 3l+cnt), cnt=3 (lane 31: 2).
    const int base = 3 * lane;
    const int cnt  = (lane == 31) ? 2 : 3;
    float d0 = s_d[warp][base],     d1 = s_d[warp][base + 1];
    float d2 = s_d[warp][base + 2];
    float d3 = (cnt == 3) ? s_d[warp][base + 3] : d2;
    float n0 = s_n[warp][base],     n1 = s_n[warp][base + 1];
    float n2 = s_n[warp][base + 2];

    float nm0 = 0.5f * (n0 + n1) - 1.0f;
    float nm1 = 0.5f * (n1 + n2) - 1.0f;
    float sp0 = (nm0 > 20.0f) ? nm0 : log1pf(expf(nm0));
    float sp1 = (nm1 > 20.0f) ? nm1 : log1pf(expf(nm1));
    float a0 = 1.0f - expf(-sp0 * (d1 - d0));
    float a1 = 1.0f - expf(-sp1 * (d2 - d1));
    float a2 = 0.0f;
    if (cnt == 3) {
        float n3  = s_n[warp][base + 3];
        float nm2 = 0.5f * (n2 + n3) - 1.0f;
        float sp2 = (nm2 > 20.0f) ? nm2 : log1pf(expf(nm2));
        a2 = 1.0f - expf(-sp2 * (d3 - d2));
    }
    s_alpha[warp][base]     = a0;
    s_alpha[warp][base + 1] = a1;
    if (cnt == 3) s_alpha[warp][base + 2] = a2;

    float f0 = 1.0f - a0 + EPSV;
    float f1 = 1.0f - a1 + EPSV;
    float f2 = (cnt == 3) ? (1.0f - a2 + EPSV) : 1.0f;

    float x = f0 * f1 * f2;                 // inclusive prefix product
    #pragma unroll
    for (int o = 1; o < 32; o <<= 1) {
        float y = __shfl_up_sync(FULLM, x, o);
        if (lane >= o) x *= y;
    }
    float T0 = __shfl_up_sync(FULLM, x, 1);
    if (lane == 0) T0 = 1.0f;
    float Tbg = __shfl_sync(FULLM, x, 31);

    float w0 = a0 * T0;
    float T1 = T0 * f0;
    float w1 = a1 * T1;
    float w2 = (cnt == 3) ? a2 * (T1 * f1) : 0.0f;

    s_w[warp][base]     = w0;
    s_w[warp][base + 1] = w1;
    if (cnt == 3) s_w[warp][base + 2] = w2;

    float wsum = w0 + w1 + w2;
    float dacc = w0 * (0.5f * (d0 + d1)) + w1 * (0.5f * (d1 + d2));
    if (cnt == 3) dacc = fmaf(w2, 0.5f * (d2 + d3), dacc);
    #pragma unroll
    for (int o = 16; o > 0; o >>= 1) {
        wsum += __shfl_xor_sync(FULLM, wsum, o);
        dacc += __shfl_xor_sync(FULLM, dacc, o);
    }
    __syncwarp();

    // v_j = w_{j-1} + w_j
    #pragma unroll
    for (int j = lane; j < NS; j += 32) {
        float wl = (j > 0)   ? s_w[warp][j - 1] : 0.0f;
        float wr = (j < SM1) ? s_w[warp][j]     : 0.0f;
        s_v[warp][j] = wl + wr;
    }
    __syncwarp();

    // ---- Phase 3: pipelined weighted color reduction, 4 batches of 24 ----
    float4 acc = make_float4(0.f, 0.f, 0.f, 0.f);
    #pragma unroll
    for (int b = 0; b < 4; b++) {
        float4 nbuf[6];
        if (b < 3) {
            #pragma unroll
            for (int k = 0; k < 6; k++)
                nbuf[k] = c4[(size_t)((b + 1) * 24 + (k << 2) + sub) * 8 + ch];
        }
        #pragma unroll
        for (int k = 0; k < 6; k++) {
            float v = s_v[warp][b * 24 + (k << 2) + sub];
            acc.x = fmaf(v, buf[k].x, acc.x);
            acc.y = fmaf(v, buf[k].y, acc.y);
            acc.z = fmaf(v, buf[k].z, acc.z);
            acc.w = fmaf(v, buf[k].w, acc.w);
        }
        if (b < 3) {
            #pragma unroll
            for (int k = 0; k < 6; k++) buf[k] = nbuf[k];
        }
    }
    #pragma unroll
    for (int o = 8; o <= 16; o <<= 1) {
        acc.x += __shfl_xor_sync(FULLM, acc.x, o);
        acc.y += __shfl_xor_sync(FULLM, acc.y, o);
        acc.z += __shfl_xor_sync(FULLM, acc.z, o);
        acc.w += __shfl_xor_sync(FULLM, acc.w, o);
    }

    // ---- Outputs: concat(rgb, depth, weights, alpha, weight_bg) ----
    float* out_rgb = out;                               // RAYS*NC
    float* out_dep = out_rgb + (size_t)RAYS * NC;       // RAYS
    float* out_w   = out_dep + RAYS;                    // RAYS*SM1
    float* out_a   = out_w   + (size_t)RAYS * SM1;      // RAYS*SM1
    float* out_bg  = out_a   + (size_t)RAYS * SM1;      // RAYS

    if (sub == 0) {
        float4 r = make_float4(acc.x - 1.f, acc.y - 1.f, acc.z - 1.f, acc.w - 1.f);
        ((float4*)(out_rgb + (size_t)ray * NC))[ch] = r;
    }

    if (lane == 0) {
        float dep = dacc / wsum;
        if (isnan(dep)) dep = INFINITY;
        dep = fminf(fmaxf(dep, s_d[warp][0]), s_d[warp][NS - 1]);
        out_dep[ray] = dep;
        out_bg[ray]  = Tbg;
    }

    #pragma unroll
    for (int j = lane; j < SM1; j += 32) {
        out_w[(size_t)ray * SM1 + j] = s_w[warp][j];
        out_a[(size_t)ray * SM1 + j] = s_alpha[warp][j];
    }
}

extern "C" void kernel_launch(void* const* d_in, const int* in_sizes, int n_in,
                              void* d_out, int out_size) {
    const float* colors    = (const float*)d_in[0];
    const float* densities = (const float*)d_in[1];
    const float* depths    = (const float*)d_in[2];
    mrm_fused<<<RAYS / 8, 256>>>(colors, densities, depths, (float*)d_out);
}

// round 5
// speedup vs baseline: 1.6383x; 1.0671x over previous
#include <cuda_runtime.h>
#include <math.h>

// Problem constants (B=4, R=4096, S=96, C=32)
#define RAYS   16384
#define NS     96
#define NC     32
#define SM1    95
#define EPSV   1e-10f
#define FULLM  0xFFFFFFFFu
#define WPB    4            // warps (rays) per block

// One warp per ray, 4 rays/block, 12 blocks/SM target.
// Identities (validated, rel_err 3.4e-6):
//  - rgb_c = sum_j v_j*c_{j,c} - 1, v_j = w_{j-1}+w_j (w_{-1}=w_95=0)
//  - global depth clamp == per-ray [d0,d95] clamp (convex combination).
__global__ __launch_bounds__(128, 12) void mrm_fused(
    const float* __restrict__ colors,     // [RAYS, NS, NC]
    const float* __restrict__ densities,  // [RAYS, NS]
    const float* __restrict__ depths,     // [RAYS, NS]
    float* __restrict__ out)
{
    __shared__ float s_d    [WPB][NS];
    __shared__ float s_n    [WPB][NS];
    __shared__ float s_alpha[WPB][NS];
    __shared__ float s_w    [WPB][NS];
    __shared__ float s_v    [WPB][NS];

    const int warp = threadIdx.x >> 5;
    const int lane = threadIdx.x & 31;
    const int ray  = blockIdx.x * WPB + warp;

    // ---- Entry: fire long-latency loads first ----
    const float4* d4 = (const float4*)(depths    + (size_t)ray * NS);
    const float4* n4 = (const float4*)(densities + (size_t)ray * NS);
    float4 dv, nv;
    if (lane < NS / 4) { dv = d4[lane]; nv = n4[lane]; }

    // color ring: lane covers sample (4i+sub), channels [8ch, 8ch+4)
    const int sub = lane >> 3;
    const int ch  = lane & 7;
    const float4* cp = (const float4*)(colors + (size_t)ray * NS * NC)
                       + (size_t)sub * 8 + ch;
    float4 buf[6];
    #pragma unroll
    for (int k = 0; k < 6; k++)
        buf[k] = __ldcs(cp + (size_t)k * 32);

    if (lane < NS / 4) {
        ((float4*)s_d[warp])[lane] = dv;
        ((float4*)s_n[warp])[lane] = nv;
    }
    __syncwarp();

    // ---- Merged phase 1+2: per-lane alphas + warp transmittance scan ----
    const int base = 3 * lane;
    const int cnt  = (lane == 31) ? 2 : 3;
    float d0 = s_d[warp][base],     d1 = s_d[warp][base + 1];
    float d2 = s_d[warp][base + 2];
    float d3 = (cnt == 3) ? s_d[warp][base + 3] : d2;
    float n0 = s_n[warp][base],     n1 = s_n[warp][base + 1];
    float n2 = s_n[warp][base + 2];

    float nm0 = 0.5f * (n0 + n1) - 1.0f;
    float nm1 = 0.5f * (n1 + n2) - 1.0f;
    float sp0 = (nm0 > 20.0f) ? nm0 : log1pf(expf(nm0));
    float sp1 = (nm1 > 20.0f) ? nm1 : log1pf(expf(nm1));
    float a0 = 1.0f - expf(-sp0 * (d1 - d0));
    float a1 = 1.0f - expf(-sp1 * (d2 - d1));
    float a2 = 0.0f;
    if (cnt == 3) {
        float n3  = s_n[warp][base + 3];
        float nm2 = 0.5f * (n2 + n3) - 1.0f;
        float sp2 = (nm2 > 20.0f) ? nm2 : log1pf(expf(nm2));
        a2 = 1.0f - expf(-sp2 * (d3 - d2));
    }
    s_alpha[warp][base]     = a0;
    s_alpha[warp][base + 1] = a1;
    if (cnt == 3) s_alpha[warp][base + 2] = a2;

    float f0 = 1.0f - a0 + EPSV;
    float f1 = 1.0f - a1 + EPSV;
    float f2 = (cnt == 3) ? (1.0f - a2 + EPSV) : 1.0f;

    float x = f0 * f1 * f2;                 // inclusive prefix product
    #pragma unroll
    for (int o = 1; o < 32; o <<= 1) {
        float y = __shfl_up_sync(FULLM, x, o);
        if (lane >= o) x *= y;
    }
    float T0 = __shfl_up_sync(FULLM, x, 1);
    if (lane == 0) T0 = 1.0f;
    float Tbg = __shfl_sync(FULLM, x, 31);

    float w0 = a0 * T0;
    float T1 = T0 * f0;
    float w1 = a1 * T1;
    float w2 = (cnt == 3) ? a2 * (T1 * f1) : 0.0f;

    s_w[warp][base]     = w0;
    s_w[warp][base + 1] = w1;
    if (cnt == 3) s_w[warp][base + 2] = w2;

    float wsum = w0 + w1 + w2;
    float dacc = w0 * (0.5f * (d0 + d1)) + w1 * (0.5f * (d1 + d2));
    if (cnt == 3) dacc = fmaf(w2, 0.5f * (d2 + d3), dacc);
    #pragma unroll
    for (int o = 16; o > 0; o >>= 1) {
        wsum += __shfl_xor_sync(FULLM, wsum, o);
        dacc += __shfl_xor_sync(FULLM, dacc, o);
    }
    __syncwarp();

    // ---- Output pointers ----
    float* out_rgb = out;                               // RAYS*NC
    float* out_dep = out_rgb + (size_t)RAYS * NC;       // RAYS
    float* out_w   = out_dep + RAYS;                    // RAYS*SM1
    float* out_a   = out_w   + (size_t)RAYS * SM1;      // RAYS*SM1
    float* out_bg  = out_a   + (size_t)RAYS * SM1;      // RAYS

    // ---- Early stores (overlap write BW with the color read stream) ----
    #pragma unroll
    for (int j = lane; j < SM1; j += 32) {
        out_w[(size_t)ray * SM1 + j] = s_w[warp][j];
        out_a[(size_t)ray * SM1 + j] = s_alpha[warp][j];
    }
    if (lane == 0) {
        float dep = dacc / wsum;
        if (isnan(dep)) dep = INFINITY;
        dep = fminf(fmaxf(dep, s_d[warp][0]), s_d[warp][NS - 1]);
        out_dep[ray] = dep;
        out_bg[ray]  = Tbg;
    }

    // v_j = w_{j-1} + w_j
    #pragma unroll
    for (int j = lane; j < NS; j += 32) {
        float wl = (j > 0)   ? s_w[warp][j - 1] : 0.0f;
        float wr = (j < SM1) ? s_w[warp][j]     : 0.0f;
        s_v[warp][j] = wl + wr;
    }
    __syncwarp();

    // ---- Phase 3: rolling-ring weighted color reduction (24 iters) ----
    float4 acc = make_float4(0.f, 0.f, 0.f, 0.f);
    #pragma unroll
    for (int i = 0; i < 24; i++) {
        float4 c = buf[i % 6];
        if (i < 18)
            buf[i % 6] = __ldcs(cp + (size_t)(i + 6) * 32);
        float v = s_v[warp][(i << 2) + sub];
        acc.x = fmaf(v, c.x, acc.x);
        acc.y = fmaf(v, c.y, acc.y);
        acc.z = fmaf(v, c.z, acc.z);
        acc.w = fmaf(v, c.w, acc.w);
    }
    #pragma unroll
    for (int o = 8; o <= 16; o <<= 1) {
        acc.x += __shfl_xor_sync(FULLM, acc.x, o);
        acc.y += __shfl_xor_sync(FULLM, acc.y, o);
        acc.z += __shfl_xor_sync(FULLM, acc.z, o);
        acc.w += __shfl_xor_sync(FULLM, acc.w, o);
    }

    if (sub == 0) {
        float4 r = make_float4(acc.x - 1.f, acc.y - 1.f, acc.z - 1.f, acc.w - 1.f);
        ((float4*)(out_rgb + (size_t)ray * NC))[ch] = r;
    }
}

extern "C" void kernel_launch(void* const* d_in, const int* in_sizes, int n_in,
                              void* d_out, int out_size) {
    const float* colors    = (const float*)d_in[0];
    const float* densities = (const float*)d_in[1];
    const float* depths    = (const float*)d_in[2];
    mrm_fused<<<RAYS / WPB, 128>>>(colors, densities, depths, (float*)d_out);
}